// round 5
// baseline (speedup 1.0000x reference)
#include <cuda_runtime.h>
#include <math.h>
#include <stdint.h>

#define Bb 4
#define Ss 4096
#define Dd 1024
#define Mm (Bb*Ss)       // 16384
#define NCHUNK 64
#define CLEN (Ss/NCHUNK) // 64

#define BM 128
#define BN 128
#define BK 64
#define NITER (Dd/BK)        // 16
#define STAGE_BYTES 32768    // Ahi 8K | Alo 8K | Whi 8K | Wlo 8K
#define NSTAGE 3
#define SMEM_DYN (NSTAGE*STAGE_BYTES)
#define QMAX 16256.0f

// ---------------- scratch (device globals) ----------------
__device__ float g_dt[(size_t)Mm*Dd];
__device__ float g_gate[(size_t)Mm*Dd];
__device__ float g_inp[(size_t)Mm*Dd];    // becomes h (fp32) in-place
__device__ float g_Ac[Bb*NCHUNK*Dd];
__device__ float g_Bc[Bb*NCHUNK*Dd];
__device__ float g_carry[Bb*NCHUNK*Dd];

__device__ __align__(16) int8_t g_qxhi[(size_t)Mm*Dd];
__device__ __align__(16) int8_t g_qxlo[(size_t)Mm*Dd];
__device__ __align__(16) int8_t g_qhhi[(size_t)Mm*Dd];
__device__ __align__(16) int8_t g_qhlo[(size_t)Mm*Dd];
__device__ __align__(16) int8_t g_qwhi[3][(size_t)Dd*Dd];
__device__ __align__(16) int8_t g_qwlo[3][(size_t)Dd*Dd];
__device__ float g_sx[Mm];
__device__ float g_sh[Mm];
__device__ float g_sw[3][Dd];

// ---------------- asm helpers (portable sm_80-era only) ----------------
__device__ __forceinline__ uint32_t smem_u32(const void* p) {
    uint32_t a;
    asm("{ .reg .u64 t; cvta.to.shared.u64 t, %1; cvt.u32.u64 %0, t; }" : "=r"(a) : "l"(p));
    return a;
}

#define CP_ASYNC16(s, g) \
    asm volatile("cp.async.cg.shared.global [%0], [%1], 16;" :: "r"(s), "l"(g))
#define CP_COMMIT() asm volatile("cp.async.commit_group;")
#define CP_WAIT1()  asm volatile("cp.async.wait_group 1;")
#define CP_WAIT0()  asm volatile("cp.async.wait_group 0;")

#define LDSM_X4(r0, r1, r2, r3, addr) \
    asm volatile("ldmatrix.sync.aligned.m8n8.x4.shared.b16 {%0,%1,%2,%3}, [%4];" \
        : "=r"(r0), "=r"(r1), "=r"(r2), "=r"(r3) : "r"(addr))

// s8 k32 MMA, s32 accumulate
#define MMA_S8(c, a, b0, b1) \
    asm volatile("mma.sync.aligned.m16n8k32.row.col.s32.s8.s8.s32 " \
        "{%0,%1,%2,%3}, {%4,%5,%6,%7}, {%8,%9}, {%0,%1,%2,%3};" \
        : "+r"((c)[0]), "+r"((c)[1]), "+r"((c)[2]), "+r"((c)[3]) \
        : "r"((a)[0]), "r"((a)[1]), "r"((a)[2]), "r"((a)[3]), "r"(b0), "r"(b1))

__device__ __forceinline__ float softplusf(float v) {
    return (v > 20.0f) ? v : log1pf(expf(v));
}

// ---------------- per-row 15-bit fixed-point quantization ----------------
// one warp per row of 1024 floats -> hi/lo s8 + per-row scale
__global__ __launch_bounds__(256)
void quant_rows(const float* __restrict__ src, int8_t* __restrict__ hi,
                int8_t* __restrict__ lo, float* __restrict__ scale)
{
    int warp = (blockIdx.x * blockDim.x + threadIdx.x) >> 5;
    int lane = threadIdx.x & 31;
    size_t base = (size_t)warp * Dd + lane * 32;

    float vals[32];
    float m = 0.0f;
    #pragma unroll
    for (int j = 0; j < 8; j++) {
        float4 v = *(const float4*)(src + base + j * 4);
        vals[j*4+0] = v.x; vals[j*4+1] = v.y; vals[j*4+2] = v.z; vals[j*4+3] = v.w;
        m = fmaxf(m, fmaxf(fmaxf(fabsf(v.x), fabsf(v.y)), fmaxf(fabsf(v.z), fabsf(v.w))));
    }
    #pragma unroll
    for (int o = 16; o > 0; o >>= 1)
        m = fmaxf(m, __shfl_xor_sync(0xFFFFFFFF, m, o));

    float s   = (m > 0.0f) ? (m / QMAX) : 1.0f;
    float inv = (m > 0.0f) ? (QMAX / m) : 0.0f;

    uint32_t hw[8], lw[8];
    #pragma unroll
    for (int j = 0; j < 8; j++) {
        uint32_t hword = 0, lword = 0;
        #pragma unroll
        for (int e = 0; e < 4; e++) {
            float q = rintf(vals[j*4+e] * inv);
            float h = rintf(q * (1.0f/128.0f));
            int hib = (int)h;
            int lob = (int)(q - 128.0f * h);
            hword |= ((uint32_t)(hib & 0xFF)) << (e * 8);
            lword |= ((uint32_t)(lob & 0xFF)) << (e * 8);
        }
        hw[j] = hword; lw[j] = lword;
    }
    *(uint4*)(hi + base)      = make_uint4(hw[0], hw[1], hw[2], hw[3]);
    *(uint4*)(hi + base + 16) = make_uint4(hw[4], hw[5], hw[6], hw[7]);
    *(uint4*)(lo + base)      = make_uint4(lw[0], lw[1], lw[2], lw[3]);
    *(uint4*)(lo + base + 16) = make_uint4(lw[4], lw[5], lw[6], lw[7]);
    if (lane == 0) scale[warp] = s;
}

// ---------------- int8 split tensor-core GEMM ----------------
// out[m,n] = sum_k A[m,k]*W[n,k],  A/W 15-bit fixed with per-row scales.
// MODE 0: g_dt = softplus(acc + dt_b[n])        aux1 = dt_b
// MODE 1: gate/inputs epilogue                  aux2 = A_log, aux3 = h0, xptr = x
// MODE 2: out = acc + Dp[n]*x                   aux1 = Dp, xptr = x
template<int MODE>
__global__ __launch_bounds__(512, 1)
void gemm_s8(float* __restrict__ out,
             const float* __restrict__ aux1, const float* __restrict__ aux2,
             const float* __restrict__ aux3, const float* __restrict__ xptr)
{
    extern __shared__ char smem[];
    const int8_t* __restrict__ Ahi = (MODE == 2) ? g_qhhi : g_qxhi;
    const int8_t* __restrict__ Alo = (MODE == 2) ? g_qhlo : g_qxlo;
    const int8_t* __restrict__ Whi = g_qwhi[MODE];
    const int8_t* __restrict__ Wlo = g_qwlo[MODE];
    const float*  __restrict__ sA  = (MODE == 2) ? g_sh : g_sx;
    const float*  __restrict__ sW  = g_sw[MODE];

    const int tid = threadIdx.x;
    const int wid = tid >> 5, lane = tid & 31;
    const int warpm = wid >> 3, warpn = wid & 7;      // 2 x 8 warps, 64x16 per warp
    const int bm = blockIdx.y * BM, bn = blockIdx.x * BN;
    const uint32_t sbase = smem_u32(smem);

    int hh[4][2][4], md[4][2][4];
    #pragma unroll
    for (int a = 0; a < 4; a++)
        #pragma unroll
        for (int b = 0; b < 2; b++)
            #pragma unroll
            for (int c = 0; c < 4; c++) { hh[a][b][c] = 0; md[a][b][c] = 0; }

    // tile layout per operand: [4 kchunks][128 rows][16B]; off = cs*2048 + row*16
    auto load_stage = [&](int s, int it) {
        uint32_t st = sbase + (uint32_t)s * STAGE_BYTES;
        int k0 = it * BK;
        int row = tid & 127, cs = tid >> 7;           // 512 threads = 4 cs x 128 rows
        uint32_t soff = (uint32_t)(cs * 2048 + row * 16);
        size_t ga = (size_t)(bm + row) * Dd + k0 + cs * 16;
        size_t gw = (size_t)(bn + row) * Dd + k0 + cs * 16;
        CP_ASYNC16(st + soff,         Ahi + ga);
        CP_ASYNC16(st + 8192  + soff, Alo + ga);
        CP_ASYNC16(st + 16384 + soff, Whi + gw);
        CP_ASYNC16(st + 24576 + soff, Wlo + gw);
        CP_COMMIT();
    };

    load_stage(0, 0);
    load_stage(1, 1);

    for (int i = 0; i < NITER; i++) {
        if (i == NITER - 1) CP_WAIT0(); else CP_WAIT1();
        __syncthreads();
        if (i + 2 < NITER) load_stage((i + 2) % NSTAGE, i + 2);

        uint32_t st = sbase + (uint32_t)(i % NSTAGE) * STAGE_BYTES;
        #pragma unroll
        for (int kk = 0; kk < 2; kk++) {              // two k32 steps per BK=64
            uint32_t csel = (uint32_t)((kk * 2 + (lane >> 4)) * 2048);
            uint32_t arow = (uint32_t)((warpm * 64 + (lane & 15)) * 16);
            uint32_t brow = (uint32_t)((warpn * 16 + (lane & 15)) * 16);
            uint32_t af[4][4], bh4[4], bl4[4];

            LDSM_X4(bh4[0], bh4[1], bh4[2], bh4[3], st + 16384 + csel + brow);
            LDSM_X4(bl4[0], bl4[1], bl4[2], bl4[3], st + 24576 + csel + brow);
            #pragma unroll
            for (int mi = 0; mi < 4; mi++)
                LDSM_X4(af[mi][0], af[mi][1], af[mi][2], af[mi][3],
                        st + csel + arow + mi * 256);

            #pragma unroll
            for (int mi = 0; mi < 4; mi++) {
                MMA_S8(hh[mi][0], af[mi], bh4[0], bh4[2]);
                MMA_S8(hh[mi][1], af[mi], bh4[1], bh4[3]);
                MMA_S8(md[mi][0], af[mi], bl4[0], bl4[2]);
                MMA_S8(md[mi][1], af[mi], bl4[1], bl4[3]);
            }
            // reuse af for A_lo
            #pragma unroll
            for (int mi = 0; mi < 4; mi++)
                LDSM_X4(af[mi][0], af[mi][1], af[mi][2], af[mi][3],
                        st + 8192 + csel + arow + mi * 256);
            #pragma unroll
            for (int mi = 0; mi < 4; mi++) {
                MMA_S8(md[mi][0], af[mi], bh4[0], bh4[2]);
                MMA_S8(md[mi][1], af[mi], bh4[1], bh4[3]);
            }
        }
    }

    // ---------------- epilogue ----------------
    const int mb0 = bm + warpm * 64;
    const int nb0 = bn + warpn * 16;
    #pragma unroll
    for (int mi = 0; mi < 4; mi++) {
        #pragma unroll
        for (int r = 0; r < 2; r++) {
            int m = mb0 + mi * 16 + (lane >> 2) + r * 8;
            size_t off = (size_t)m * Dd;
            float sa = sA[m];
            #pragma unroll
            for (int ni = 0; ni < 2; ni++) {
                int n = nb0 + ni * 8 + (lane & 3) * 2;
                float2 sw2 = *(const float2*)&sW[n];
                float f0 = (float)hh[mi][ni][r*2]   * 16384.0f + (float)md[mi][ni][r*2]   * 128.0f;
                float f1 = (float)hh[mi][ni][r*2+1] * 16384.0f + (float)md[mi][ni][r*2+1] * 128.0f;
                float v0 = f0 * sa * sw2.x;
                float v1 = f1 * sa * sw2.y;
                if (MODE == 0) {
                    float2 bv = *(const float2*)&aux1[n];
                    float2 o;
                    o.x = softplusf(v0 + bv.x);
                    o.y = softplusf(v1 + bv.y);
                    *(float2*)&g_dt[off + n] = o;
                } else if (MODE == 1) {
                    float2 dt = *(const float2*)&g_dt[off + n];
                    float2 al2 = *(const float2*)&aux2[n];
                    float2 xv = *(const float2*)&xptr[off + n];
                    float2 gv, iv;
                    gv.x = expf(dt.x * (-expf(al2.x)));
                    gv.y = expf(dt.y * (-expf(al2.y)));
                    iv.x = dt.x * v0 * xv.x;
                    iv.y = dt.y * v1 * xv.y;
                    if ((m & (Ss - 1)) == 0) {
                        int b = m / Ss;
                        float2 h0v = *(const float2*)&aux3[(size_t)b * Dd + n];
                        iv.x += gv.x * h0v.x;
                        iv.y += gv.y * h0v.y;
                    }
                    *(float2*)&g_gate[off + n] = gv;
                    *(float2*)&g_inp[off + n] = iv;
                } else {
                    float2 dp = *(const float2*)&aux1[n];
                    float2 xv = *(const float2*)&xptr[off + n];
                    float2 o;
                    o.x = v0 + dp.x * xv.x;
                    o.y = v1 + dp.y * xv.y;
                    *(float2*)&out[off + n] = o;
                }
            }
        }
    }
}

// ---------------- chunked associative scan ----------------
__global__ void scan_pass1()
{
    int idx = blockIdx.x * blockDim.x + threadIdx.x;
    int d = idx & (Dd - 1);
    int chunk = (idx / Dd) & (NCHUNK - 1);
    int b = idx / (Dd * NCHUNK);
    size_t base = ((size_t)b * Ss + (size_t)chunk * CLEN) * Dd + d;
    float a = 1.0f, h = 0.0f;
    #pragma unroll 8
    for (int t = 0; t < CLEN; t++) {
        float g  = g_gate[base + (size_t)t * Dd];
        float in = g_inp [base + (size_t)t * Dd];
        a *= g;
        h = g * h + in;
    }
    g_Ac[idx] = a;
    g_Bc[idx] = h;
}

__global__ void scan_pass2()
{
    int idx = blockIdx.x * blockDim.x + threadIdx.x;   // b*D + d
    int d = idx & (Dd - 1);
    int b = idx / Dd;
    const int base = b * NCHUNK * Dd + d;

    float A0[8], B0[8], A1[8], B1[8];
    #pragma unroll
    for (int j = 0; j < 8; j++) {
        A0[j] = g_Ac[base + j * Dd];
        B0[j] = g_Bc[base + j * Dd];
    }
    float c = 0.0f;
    #pragma unroll
    for (int ch = 0; ch < 8; ch++) {
        if (ch < 7) {
            #pragma unroll
            for (int j = 0; j < 8; j++) {
                A1[j] = g_Ac[base + ((ch + 1) * 8 + j) * Dd];
                B1[j] = g_Bc[base + ((ch + 1) * 8 + j) * Dd];
            }
        }
        #pragma unroll
        for (int j = 0; j < 8; j++) {
            g_carry[base + (ch * 8 + j) * Dd] = c;
            c = A0[j] * c + B0[j];
        }
        #pragma unroll
        for (int j = 0; j < 8; j++) { A0[j] = A1[j]; B0[j] = B1[j]; }
    }
}

__global__ void scan_pass3()
{
    int idx = blockIdx.x * blockDim.x + threadIdx.x;
    int d = idx & (Dd - 1);
    int chunk = (idx / Dd) & (NCHUNK - 1);
    int b = idx / (Dd * NCHUNK);
    size_t base = ((size_t)b * Ss + (size_t)chunk * CLEN) * Dd + d;
    float h = g_carry[idx];
    #pragma unroll 8
    for (int t = 0; t < CLEN; t++) {
        size_t o = base + (size_t)t * Dd;
        h = g_gate[o] * h + g_inp[o];
        g_inp[o] = h;                      // h_all, fp32 in place
    }
}

extern "C" void kernel_launch(void* const* d_in, const int* in_sizes, int n_in,
                              void* d_out, int out_size)
{
    const float* x     = (const float*)d_in[0];
    const float* h0    = (const float*)d_in[1];
    const float* dt_w  = (const float*)d_in[2];
    const float* dt_b  = (const float*)d_in[3];
    const float* A_log = (const float*)d_in[4];
    const float* B_w   = (const float*)d_in[5];
    const float* C_w   = (const float*)d_in[6];
    const float* Dp    = (const float*)d_in[7];
    float* out = (float*)d_out;

    cudaFuncSetAttribute(gemm_s8<0>, cudaFuncAttributeMaxDynamicSharedMemorySize, SMEM_DYN);
    cudaFuncSetAttribute(gemm_s8<1>, cudaFuncAttributeMaxDynamicSharedMemorySize, SMEM_DYN);
    cudaFuncSetAttribute(gemm_s8<2>, cudaFuncAttributeMaxDynamicSharedMemorySize, SMEM_DYN);

    int8_t *qxhi, *qxlo, *qhhi, *qhlo, *qw0h, *qw0l, *qw1h, *qw1l, *qw2h, *qw2l;
    float *sx, *sh, *sw0, *sw1, *sw2, *inp;
    cudaGetSymbolAddress((void**)&qxhi, g_qxhi);
    cudaGetSymbolAddress((void**)&qxlo, g_qxlo);
    cudaGetSymbolAddress((void**)&qhhi, g_qhhi);
    cudaGetSymbolAddress((void**)&qhlo, g_qhlo);
    cudaGetSymbolAddress((void**)&qw0h, g_qwhi); qw1h = qw0h + (size_t)Dd*Dd; qw2h = qw1h + (size_t)Dd*Dd;
    cudaGetSymbolAddress((void**)&qw0l, g_qwlo); qw1l = qw0l + (size_t)Dd*Dd; qw2l = qw1l + (size_t)Dd*Dd;
    cudaGetSymbolAddress((void**)&sx, g_sx);
    cudaGetSymbolAddress((void**)&sh, g_sh);
    cudaGetSymbolAddress((void**)&sw0, g_sw); sw1 = sw0 + Dd; sw2 = sw1 + Dd;
    cudaGetSymbolAddress((void**)&inp, g_inp);

    // quantize inputs (one warp per row, 8 rows per 256-thread block)
    quant_rows<<<Mm / 8, 256>>>(x, qxhi, qxlo, sx);
    quant_rows<<<Dd / 8, 256>>>(dt_w, qw0h, qw0l, sw0);
    quant_rows<<<Dd / 8, 256>>>(B_w,  qw1h, qw1l, sw1);
    quant_rows<<<Dd / 8, 256>>>(C_w,  qw2h, qw2l, sw2);

    dim3 grid(Dd / BN, Mm / BM);   // (8, 128)
    dim3 blk(512);

    gemm_s8<0><<<grid, blk, SMEM_DYN>>>(nullptr, dt_b, nullptr, nullptr, nullptr);
    gemm_s8<1><<<grid, blk, SMEM_DYN>>>(nullptr, nullptr, A_log, h0, x);
    scan_pass1<<<(Bb * NCHUNK * Dd) / 256, 256>>>();
    scan_pass2<<<(Bb * Dd) / 256, 256>>>();
    scan_pass3<<<(Bb * NCHUNK * Dd) / 256, 256>>>();
    quant_rows<<<Mm / 8, 256>>>(inp, qhhi, qhlo, sh);   // quantize h
    gemm_s8<2><<<grid, blk, SMEM_DYN>>>(out, Dp, nullptr, nullptr, x);
}

// round 7
// speedup vs baseline: 6.0907x; 6.0907x over previous
#include <cuda_runtime.h>
#include <cuda_fp16.h>
#include <math.h>
#include <stdint.h>

#define Bb 4
#define Ss 4096
#define Dd 1024
#define Mm (Bb*Ss)       // 16384
#define NCHUNK 64
#define CLEN (Ss/NCHUNK) // 64

#define BM 128
#define BN 128
#define BK 32
#define NITER (Dd/BK)        // 32
#define STAGE_BYTES 16384    // A 8K | W 8K
#define NSTAGE 3
#define SMEM_DYN (NSTAGE*STAGE_BYTES)

// ---------------- scratch (device globals) ----------------
__device__ float g_dt[(size_t)Mm*Dd];
__device__ float g_gate[(size_t)Mm*Dd];
__device__ float g_inp[(size_t)Mm*Dd];    // becomes h (fp32) in-place
__device__ float g_Ac[Bb*NCHUNK*Dd];
__device__ float g_Bc[Bb*NCHUNK*Dd];
__device__ float g_carry[Bb*NCHUNK*Dd];

__device__ __align__(16) __half g_x16[(size_t)Mm*Dd];
__device__ __align__(16) __half g_h16[(size_t)Mm*Dd];
__device__ __align__(16) __half g_w16[3][(size_t)Dd*Dd];

// ---------------- asm helpers (portable sm_80-era only) ----------------
__device__ __forceinline__ uint32_t smem_u32(const void* p) {
    uint32_t a;
    asm("{ .reg .u64 t; cvta.to.shared.u64 t, %1; cvt.u32.u64 %0, t; }" : "=r"(a) : "l"(p));
    return a;
}

#define CP_ASYNC16(s, g) \
    asm volatile("cp.async.cg.shared.global [%0], [%1], 16;" :: "r"(s), "l"(g))
#define CP_COMMIT() asm volatile("cp.async.commit_group;")
#define CP_WAIT1()  asm volatile("cp.async.wait_group 1;")
#define CP_WAIT0()  asm volatile("cp.async.wait_group 0;")

#define LDSM_X4(r0, r1, r2, r3, addr) \
    asm volatile("ldmatrix.sync.aligned.m8n8.x4.shared.b16 {%0,%1,%2,%3}, [%4];" \
        : "=r"(r0), "=r"(r1), "=r"(r2), "=r"(r3) : "r"(addr))

#define MMA_F16(c, a, b0, b1) \
    asm volatile("mma.sync.aligned.m16n8k16.row.col.f32.f16.f16.f32 " \
        "{%0,%1,%2,%3}, {%4,%5,%6,%7}, {%8,%9}, {%0,%1,%2,%3};" \
        : "+f"((c)[0]), "+f"((c)[1]), "+f"((c)[2]), "+f"((c)[3]) \
        : "r"((a)[0]), "r"((a)[1]), "r"((a)[2]), "r"((a)[3]), "r"(b0), "r"(b1))

__device__ __forceinline__ float softplusf(float v) {
    return (v > 20.0f) ? v : log1pf(expf(v));
}

// smem offset for (row, 16B-chunk c): 64B rows, XOR swizzle for conflict-free ldmatrix
__device__ __forceinline__ uint32_t swz(int row, int c) {
    return (uint32_t)(row * 64 + ((c ^ ((row >> 1) & 3)) << 4));
}

// ---------------- fp32 -> fp16 conversion ----------------
template<int DST>
__global__ void conv_f16(const float* __restrict__ src)
{
    size_t i = ((size_t)blockIdx.x * blockDim.x + threadIdx.x) * 8;
    __half* dst;
    if (DST == 0)      dst = g_x16;
    else if (DST == 1) dst = g_w16[0];
    else if (DST == 2) dst = g_w16[1];
    else               dst = g_w16[2];
    float4 v0 = *(const float4*)(src + i);
    float4 v1 = *(const float4*)(src + i + 4);
    __half2* d2 = (__half2*)(dst + i);
    d2[0] = __floats2half2_rn(v0.x, v0.y);
    d2[1] = __floats2half2_rn(v0.z, v0.w);
    d2[2] = __floats2half2_rn(v1.x, v1.y);
    d2[3] = __floats2half2_rn(v1.z, v1.w);
}

// ---------------- fp16 single-pass tensor-core GEMM ----------------
// out[m,n] = sum_k A[m,k] * W[n,k]
// MODE 0: g_dt = softplus(acc + dt_b[n])        aux1 = dt_b
// MODE 1: gate/inputs epilogue                  aux2 = A_log, aux3 = h0, xptr = x
// MODE 2: out = acc + Dp[n]*x                   aux1 = Dp, xptr = x
template<int MODE>
__global__ __launch_bounds__(256, 2)
void gemm_f16(float* __restrict__ out,
              const float* __restrict__ aux1, const float* __restrict__ aux2,
              const float* __restrict__ aux3, const float* __restrict__ xptr)
{
    extern __shared__ char smem[];
    const __half* __restrict__ A = (MODE == 2) ? g_h16 : g_x16;
    const __half* __restrict__ W = g_w16[MODE];

    const int tid = threadIdx.x;
    const int wid = tid >> 5, lane = tid & 31;
    const int warpm = wid >> 2, warpn = wid & 3;      // 2 x 4 warps, 64x32 per warp
    const int bm = blockIdx.y * BM, bn = blockIdx.x * BN;
    const uint32_t sbase = smem_u32(smem);

    float acc[4][4][4];
    #pragma unroll
    for (int a = 0; a < 4; a++)
        #pragma unroll
        for (int b = 0; b < 4; b++)
            #pragma unroll
            for (int c = 0; c < 4; c++) acc[a][b][c] = 0.0f;

    auto load_stage = [&](int s, int it) {
        uint32_t st = sbase + (uint32_t)s * STAGE_BYTES;
        int k0 = it * BK;
        #pragma unroll
        for (int p = 0; p < 2; p++) {
            int lin = tid + p * 256;       // 0..511 chunks per array
            int row = lin >> 2, c = lin & 3;
            uint32_t soff = swz(row, c);
            size_t ga = (size_t)(bm + row) * Dd + k0 + c * 8;
            size_t gw = (size_t)(bn + row) * Dd + k0 + c * 8;
            CP_ASYNC16(st + soff,        A + ga);
            CP_ASYNC16(st + 8192 + soff, W + gw);
        }
        CP_COMMIT();
    };

    load_stage(0, 0);
    load_stage(1, 1);

    for (int i = 0; i < NITER; i++) {
        if (i == NITER - 1) CP_WAIT0(); else CP_WAIT1();
        __syncthreads();
        if (i + 2 < NITER) load_stage((i + 2) % NSTAGE, i + 2);

        uint32_t st = sbase + (uint32_t)(i % NSTAGE) * STAGE_BYTES;
        #pragma unroll
        for (int kk = 0; kk < 2; kk++) {       // two k16 steps per BK=32 stage
            uint32_t ah[4][4], bh[2][4];
            #pragma unroll
            for (int mi = 0; mi < 4; mi++) {
                int row = warpm * 64 + mi * 16 + (lane & 15);
                int c = kk * 2 + (lane >> 4);
                LDSM_X4(ah[mi][0], ah[mi][1], ah[mi][2], ah[mi][3], st + swz(row, c));
            }
            #pragma unroll
            for (int pr = 0; pr < 2; pr++) {
                int row = warpn * 32 + pr * 16 + (lane & 7) + (((lane >> 4) & 1) << 3);
                int c = kk * 2 + ((lane >> 3) & 1);
                LDSM_X4(bh[pr][0], bh[pr][1], bh[pr][2], bh[pr][3], st + 8192 + swz(row, c));
            }
            #pragma unroll
            for (int mi = 0; mi < 4; mi++)
                #pragma unroll
                for (int ni = 0; ni < 4; ni++)
                    MMA_F16(acc[mi][ni], ah[mi], bh[ni >> 1][(ni & 1) * 2], bh[ni >> 1][(ni & 1) * 2 + 1]);
        }
    }

    // ---------------- epilogue ----------------
    const int mb0 = bm + warpm * 64;
    const int nb0 = bn + warpn * 32;
    #pragma unroll
    for (int mi = 0; mi < 4; mi++) {
        #pragma unroll
        for (int r = 0; r < 2; r++) {
            int m = mb0 + mi * 16 + (lane >> 2) + r * 8;
            size_t off = (size_t)m * Dd;
            #pragma unroll
            for (int ni = 0; ni < 4; ni++) {
                int n = nb0 + ni * 8 + (lane & 3) * 2;
                float v0 = acc[mi][ni][r * 2], v1 = acc[mi][ni][r * 2 + 1];
                if (MODE == 0) {
                    float2 bv = *(const float2*)&aux1[n];
                    float2 o;
                    o.x = softplusf(v0 + bv.x);
                    o.y = softplusf(v1 + bv.y);
                    *(float2*)&g_dt[off + n] = o;
                } else if (MODE == 1) {
                    float2 dt = *(const float2*)&g_dt[off + n];
                    float2 al2 = *(const float2*)&aux2[n];
                    float2 xv = *(const float2*)&xptr[off + n];
                    float2 gv, iv;
                    gv.x = expf(dt.x * (-expf(al2.x)));
                    gv.y = expf(dt.y * (-expf(al2.y)));
                    iv.x = dt.x * v0 * xv.x;
                    iv.y = dt.y * v1 * xv.y;
                    if ((m & (Ss - 1)) == 0) {
                        int b = m / Ss;
                        float2 h0v = *(const float2*)&aux3[(size_t)b * Dd + n];
                        iv.x += gv.x * h0v.x;
                        iv.y += gv.y * h0v.y;
                    }
                    *(float2*)&g_gate[off + n] = gv;
                    *(float2*)&g_inp[off + n] = iv;
                } else {
                    float2 dp = *(const float2*)&aux1[n];
                    float2 xv = *(const float2*)&xptr[off + n];
                    float2 o;
                    o.x = v0 + dp.x * xv.x;
                    o.y = v1 + dp.y * xv.y;
                    *(float2*)&out[off + n] = o;
                }
            }
        }
    }
}

// ---------------- chunked associative scan ----------------
__global__ void scan_pass1()
{
    int idx = blockIdx.x * blockDim.x + threadIdx.x;
    int d = idx & (Dd - 1);
    int chunk = (idx / Dd) & (NCHUNK - 1);
    int b = idx / (Dd * NCHUNK);
    size_t base = ((size_t)b * Ss + (size_t)chunk * CLEN) * Dd + d;
    float a = 1.0f, h = 0.0f;
    #pragma unroll 8
    for (int t = 0; t < CLEN; t++) {
        float g  = g_gate[base + (size_t)t * Dd];
        float in = g_inp [base + (size_t)t * Dd];
        a *= g;
        h = g * h + in;
    }
    g_Ac[idx] = a;
    g_Bc[idx] = h;
}

__global__ void scan_pass2()
{
    int idx = blockIdx.x * blockDim.x + threadIdx.x;   // b*D + d
    int d = idx & (Dd - 1);
    int b = idx / Dd;
    const int base = b * NCHUNK * Dd + d;

    float A0[8], B0[8], A1[8], B1[8];
    #pragma unroll
    for (int j = 0; j < 8; j++) {
        A0[j] = g_Ac[base + j * Dd];
        B0[j] = g_Bc[base + j * Dd];
    }
    float c = 0.0f;
    #pragma unroll
    for (int ch = 0; ch < 8; ch++) {
        if (ch < 7) {
            #pragma unroll
            for (int j = 0; j < 8; j++) {
                A1[j] = g_Ac[base + ((ch + 1) * 8 + j) * Dd];
                B1[j] = g_Bc[base + ((ch + 1) * 8 + j) * Dd];
            }
        }
        #pragma unroll
        for (int j = 0; j < 8; j++) {
            g_carry[base + (ch * 8 + j) * Dd] = c;
            c = A0[j] * c + B0[j];
        }
        #pragma unroll
        for (int j = 0; j < 8; j++) { A0[j] = A1[j]; B0[j] = B1[j]; }
    }
}

__global__ void scan_pass3()
{
    int idx = blockIdx.x * blockDim.x + threadIdx.x;
    int d = idx & (Dd - 1);
    int chunk = (idx / Dd) & (NCHUNK - 1);
    int b = idx / (Dd * NCHUNK);
    size_t base = ((size_t)b * Ss + (size_t)chunk * CLEN) * Dd + d;
    float h = g_carry[idx];
    #pragma unroll 8
    for (int t = 0; t < CLEN; t++) {
        size_t o = base + (size_t)t * Dd;
        h = g_gate[o] * h + g_inp[o];
        g_h16[o] = __float2half(h);
    }
}

extern "C" void kernel_launch(void* const* d_in, const int* in_sizes, int n_in,
                              void* d_out, int out_size)
{
    const float* x     = (const float*)d_in[0];
    const float* h0    = (const float*)d_in[1];
    const float* dt_w  = (const float*)d_in[2];
    const float* dt_b  = (const float*)d_in[3];
    const float* A_log = (const float*)d_in[4];
    const float* B_w   = (const float*)d_in[5];
    const float* C_w   = (const float*)d_in[6];
    const float* Dp    = (const float*)d_in[7];
    float* out = (float*)d_out;

    cudaFuncSetAttribute(gemm_f16<0>, cudaFuncAttributeMaxDynamicSharedMemorySize, SMEM_DYN);
    cudaFuncSetAttribute(gemm_f16<1>, cudaFuncAttributeMaxDynamicSharedMemorySize, SMEM_DYN);
    cudaFuncSetAttribute(gemm_f16<2>, cudaFuncAttributeMaxDynamicSharedMemorySize, SMEM_DYN);

    conv_f16<0><<<((size_t)Mm * Dd) / 2048, 256>>>(x);
    conv_f16<1><<<((size_t)Dd * Dd) / 2048, 256>>>(dt_w);
    conv_f16<2><<<((size_t)Dd * Dd) / 2048, 256>>>(B_w);
    conv_f16<3><<<((size_t)Dd * Dd) / 2048, 256>>>(C_w);

    dim3 grid(Dd / BN, Mm / BM);   // (8, 128)
    dim3 blk(256);

    gemm_f16<0><<<grid, blk, SMEM_DYN>>>(nullptr, dt_b, nullptr, nullptr, nullptr);
    gemm_f16<1><<<grid, blk, SMEM_DYN>>>(nullptr, nullptr, A_log, h0, x);
    scan_pass1<<<(Bb * NCHUNK * Dd) / 256, 256>>>();
    scan_pass2<<<(Bb * Dd) / 256, 256>>>();
    scan_pass3<<<(Bb * NCHUNK * Dd) / 256, 256>>>();
    gemm_f16<2><<<grid, blk, SMEM_DYN>>>(out, Dp, nullptr, nullptr, x);
}